// round 11
// baseline (speedup 1.0000x reference)
#include <cuda_runtime.h>
#include <cstdint>

// z: (64,13,128,128) fp32
#define BB 64
#define CC 13
#define HWSZ 16384                       // 128*128
#define NPIX (BB*HWSZ)                   // 1,048,576
#define NTOT (CC*NPIX)                   // 13,631,488

#define THREADS 256
#define TILE 1024                        // pixels per block (one image, contiguous)
#define F_BLOCKS (NPIX / TILE)           // 1024
#define TILES_PER_IMG (HWSZ / TILE)      // 16

// Deterministic scratch (fully overwritten every launch; no runtime allocs).
// Per-block row of 16 floats: [commit, ent, ch0..ch12, pad]
__device__ float g_partials[F_BLOCKS * 16];
// Self-resetting ticket: atomicInc wraps to 0 after F_BLOCKS increments.
__device__ unsigned int g_ticket;

__device__ __forceinline__ float warp_sum(float v) {
    #pragma unroll
    for (int o = 16; o; o >>= 1) v += __shfl_xor_sync(0xffffffffu, v, o);
    return v;
}

__device__ __forceinline__ void proc(float zv, float& q, float& commit,
                                     float& ent, float& ca, int& idx) {
    bool pos = zv > 0.0f;
    q = pos ? 1.0f : -1.0f;
    float az = fabsf(zv);
    float d = 1.0f - az;
    commit = fmaf(d, d, commit);
    float a = 4.0f * az;                  // |l0 - l1|
    float e = __expf(-a);                 // in (0,1]
    float r = __fdividef(1.0f, 1.0f + e); // sigmoid(a)
    float ps = e * r;                     // 1 - sigmoid(a)
    ent += fmaf(a, ps, __logf(1.0f + e)); // H(p)
    ca += pos ? r : ps;                   // p0 = sigmoid(4z)
    idx = (idx << 1) | (pos ? 1 : 0);     // MSB = channel 0
}

__global__ void __launch_bounds__(THREADS)
lfq_fused(const float* __restrict__ z, float* __restrict__ out) {
    int tid = threadIdx.x;
    int blk = blockIdx.x;
    int b    = blk >> 4;                  // image
    int tile = blk & (TILES_PER_IMG - 1);

    size_t zoff = (size_t)b * (CC * HWSZ) + tile * TILE + tid * 4;

    __shared__ float s_ch[CC][THREADS];   // per-thread per-channel partial (no atomics)
    __shared__ float sw[2][8];

    float commit = 0.0f, ent = 0.0f;
    int i0 = 0, i1 = 0, i2 = 0, i3 = 0;

    // depth-2 prefetch over channels
    float4 p0 = *reinterpret_cast<const float4*>(z + zoff);
    float4 p1 = *reinterpret_cast<const float4*>(z + zoff + HWSZ);
    #pragma unroll 1
    for (int c = 0; c < CC; c++) {
        float4 v = p0;
        p0 = p1;
        if (c + 2 < CC)
            p1 = *reinterpret_cast<const float4*>(z + zoff + (size_t)(c + 2) * HWSZ);
        float4 q;
        float ca = 0.0f;
        proc(v.x, q.x, commit, ent, ca, i0);
        proc(v.y, q.y, commit, ent, ca, i1);
        proc(v.z, q.z, commit, ent, ca, i2);
        proc(v.w, q.w, commit, ent, ca, i3);
        *reinterpret_cast<float4*>(out + zoff + (size_t)c * HWSZ) = q;
        s_ch[c][tid] = ca;
    }

    // indices straight from registers (8B-aligned region -> float2 stores)
    float* idx_out = out + NTOT + 2;
    int pix = blk * TILE + tid * 4;
    *reinterpret_cast<float2*>(idx_out + pix)     = make_float2((float)i0, (float)i1);
    *reinterpret_cast<float2*>(idx_out + pix + 2) = make_float2((float)i2, (float)i3);

    // ---- block reductions ----
    commit = warp_sum(commit);
    ent    = warp_sum(ent);
    int w = tid >> 5, lane = tid & 31;
    if (lane == 0) { sw[0][w] = commit; sw[1][w] = ent; }
    __syncthreads();

    for (int ch = w; ch < CC; ch += 8) {
        float v = 0.0f;
        #pragma unroll
        for (int k = 0; k < THREADS / 32; k++) v += s_ch[ch][lane + 32 * k];
        v = warp_sum(v);
        if (lane == 0) g_partials[blk * 16 + 2 + ch] = v;
    }
    if (tid == 0) {
        float c0 = 0.0f, e0 = 0.0f;
        #pragma unroll
        for (int i = 0; i < 8; i++) { c0 += sw[0][i]; e0 += sw[1][i]; }
        g_partials[blk * 16 + 0] = c0;
        g_partials[blk * 16 + 1] = e0;
    }

    // ---- last-block-done finalize (fast float4 row reads, MLP 16) ----
    __shared__ bool is_last;
    __threadfence();
    if (tid == 0) {
        unsigned int old = atomicInc(&g_ticket, F_BLOCKS - 1);  // wraps to 0
        is_last = (old == F_BLOCKS - 1);
    }
    __syncthreads();
    if (!is_last) return;
    __threadfence();

    float4 a0 = make_float4(0,0,0,0), a1 = a0, a2 = a0, a3 = a0;
    #pragma unroll
    for (int r = 0; r < F_BLOCKS / THREADS; r++) {               // 4 rows/thread
        const float4* row = reinterpret_cast<const float4*>(
            &g_partials[(r * THREADS + tid) * 16]);
        float4 v0 = row[0], v1 = row[1], v2 = row[2], v3 = row[3];
        a0.x += v0.x; a0.y += v0.y; a0.z += v0.z; a0.w += v0.w;
        a1.x += v1.x; a1.y += v1.y; a1.z += v1.z; a1.w += v1.w;
        a2.x += v2.x; a2.y += v2.y; a2.z += v2.z; a2.w += v2.w;
        a3.x += v3.x; a3.y += v3.y; a3.z += v3.z; a3.w += v3.w;
    }
    float acc[16] = {a0.x,a0.y,a0.z,a0.w, a1.x,a1.y,a1.z,a1.w,
                     a2.x,a2.y,a2.z,a2.w, a3.x,a3.y,a3.z,a3.w};
    #pragma unroll
    for (int i = 0; i < 16; i++) acc[i] = warp_sum(acc[i]);

    __shared__ float sacc[8][16];
    if (lane == 0) {
        #pragma unroll
        for (int i = 0; i < 16; i++) sacc[w][i] = acc[i];
    }
    __syncthreads();

    __shared__ float S[16];
    if (tid < 16) {
        float v = 0.0f;
        #pragma unroll
        for (int i = 0; i < 8; i++) v += sacc[i][tid];
        S[tid] = v;                      // S[0]=commit, S[1]=ent, S[2..14]=ch sums
    }
    __syncthreads();

    __shared__ float sment;
    if (tid < 32) {
        float me = 0.0f;
        if (tid < CC) {
            float mp = S[2 + tid] * (1.0f / (float)NPIX);
            mp = fminf(fmaxf(mp, 1e-12f), 1.0f - 1e-7f);
            float mq = 1.0f - mp;
            me = -(mp * __logf(mp) + mq * __logf(mq));
        }
        me = warp_sum(me);
        if (tid == 0) sment = me * (1.0f / (float)CC);
    }
    __syncthreads();

    if (tid == 0) {
        out[NTOT]     = S[0] * (float)(1.25 * 0.1 / (double)NTOT);
        out[NTOT + 1] = (S[1] * (float)(1.0 / (double)NTOT) - sment) * 0.1f;
    }
}

extern "C" void kernel_launch(void* const* d_in, const int* in_sizes, int n_in,
                              void* d_out, int out_size) {
    const float* z = (const float*)d_in[0];
    float* out = (float*)d_out;
    lfq_fused<<<F_BLOCKS, THREADS>>>(z, out);
}

// round 12
// speedup vs baseline: 1.3750x; 1.3750x over previous
#include <cuda_runtime.h>
#include <cstdint>

// z: (64,13,128,128) fp32
#define BB 64
#define CC 13
#define HWSZ 16384                       // 128*128
#define NPIX (BB*HWSZ)                   // 1,048,576
#define NTOT (CC*NPIX)                   // 13,631,488
#define NPLANES (BB*CC)                  // 832
#define THREADS 256

// Kernel A: each block = one quarter (4096 floats) of one (b,c) plane.
#define A_BLOCKS (NPLANES*4)             // 3328
#define SLOTS 256                        // per-channel partial slots (64 imgs * 4 quarters)

// Deterministic scratch (fully overwritten every launch; no runtime allocs).
__device__ float2 g_ce[A_BLOCKS];                 // per-block {commit, ent}
__device__ float g_chsum[CC * SLOTS];             // channel-major p0 partials
__device__ unsigned char g_signs[NTOT/4];         // 4 sign bits/byte (low nibble)

__device__ __forceinline__ float warp_sum(float v) {
    #pragma unroll
    for (int o = 16; o; o >>= 1) v += __shfl_xor_sync(0xffffffffu, v, o);
    return v;
}

__device__ __forceinline__ void proc(float zv, float& q, float& commit,
                                     float& ent, float& ch, unsigned& byte, int k) {
    bool pos = zv > 0.0f;
    q = pos ? 1.0f : -1.0f;
    float az = fabsf(zv);
    float d = 1.0f - az;
    commit = fmaf(d, d, commit);
    float a = 4.0f * az;                  // |l0 - l1|
    float e = __expf(-a);                 // in (0,1]
    float r = __fdividef(1.0f, 1.0f + e); // sigmoid(a)
    float ps = e * r;                     // 1 - sigmoid(a)
    ent += fmaf(a, ps, __logf(1.0f + e)); // H(p)
    ch += pos ? r : ps;                   // p0 = sigmoid(4z)
    byte |= (pos ? 1u : 0u) << k;
}

// ---------------- Kernel A: quantize + partial sums + sign bytes ----------------
__global__ void __launch_bounds__(THREADS)
lfq_planes(const float* __restrict__ z, float* __restrict__ out) {
    int tid = threadIdx.x;
    int blk = blockIdx.x;
    int p       = blk >> 2;               // plane id = b*13 + c
    int quarter = blk & 3;
    size_t base = (size_t)p * HWSZ + quarter * 4096 + tid * 4;

    float4 v[4];
    #pragma unroll
    for (int i = 0; i < 4; i++)
        v[i] = *reinterpret_cast<const float4*>(z + base + i * 1024);

    float commit = 0.0f, ent = 0.0f, ch = 0.0f;
    int sbase = p * 4096 + quarter * 1024 + tid;
    #pragma unroll
    for (int i = 0; i < 4; i++) {
        float4 q;
        unsigned byte = 0;
        proc(v[i].x, q.x, commit, ent, ch, byte, 0);
        proc(v[i].y, q.y, commit, ent, ch, byte, 1);
        proc(v[i].z, q.z, commit, ent, ch, byte, 2);
        proc(v[i].w, q.w, commit, ent, ch, byte, 3);
        *reinterpret_cast<float4*>(out + base + i * 1024) = q;
        g_signs[sbase + i * 256] = (unsigned char)byte;   // byte s covers pixels 4s..4s+3
    }

    // deterministic block reduction of 3 scalars
    commit = warp_sum(commit);
    ent    = warp_sum(ent);
    ch     = warp_sum(ch);
    __shared__ float sw[3][8];
    int w = tid >> 5;
    if ((tid & 31) == 0) { sw[0][w] = commit; sw[1][w] = ent; sw[2][w] = ch; }
    __syncthreads();
    if (tid == 0) {
        float c0 = 0, e0 = 0, h0 = 0;
        #pragma unroll
        for (int i = 0; i < 8; i++) { c0 += sw[0][i]; e0 += sw[1][i]; h0 += sw[2][i]; }
        g_ce[blk] = make_float2(c0, e0);
        int b = p / CC, c = p - b * CC;
        g_chsum[c * SLOTS + b * 4 + quarter] = h0;    // channel-major
    }
}

// -------- Kernel B: blocks 0..511 pack indices (4 px/thread); block 512 finalizes
#define PACK_BLOCKS 512

__global__ void __launch_bounds__(512)
lfq_pack_finalize(float* __restrict__ out) {
    int tid = threadIdx.x;

    if (blockIdx.x < PACK_BLOCKS) {
        float* idx_out = out + NTOT + 2;        // 8B-aligned region -> float2 stores
        int g = blockIdx.x * 512 + tid;         // pixel-group id, [0, NPIX/4)
        int b = g >> 12;                        // 4096 groups per batch image
        int local = g & 4095;
        int i0 = 0, i1 = 0, i2 = 0, i3 = 0;
        #pragma unroll
        for (int c = 0; c < CC; c++) {          // MSB = channel 0
            unsigned byte = g_signs[(b * CC + c) * 4096 + local];
            i0 = (i0 << 1) | (byte & 1);
            i1 = (i1 << 1) | ((byte >> 1) & 1);
            i2 = (i2 << 1) | ((byte >> 2) & 1);
            i3 = (i3 << 1) | ((byte >> 3) & 1);
        }
        int pix = g * 4;
        *reinterpret_cast<float2*>(idx_out + pix)     = make_float2((float)i0, (float)i1);
        *reinterpret_cast<float2*>(idx_out + pix + 2) = make_float2((float)i2, (float)i3);
        return;
    }

    // ---------------- finalize block: fast coalesced reads, fp32 logs ----------
    int w = tid >> 5, lane = tid & 31;
    __shared__ float sce[2][16];
    __shared__ float sch[CC];
    __shared__ float sment;

    // commit/ent: 3328 contiguous float2, strided by 512 threads (<=7 iters, coalesced)
    float commit = 0.0f, ent = 0.0f;
    #pragma unroll
    for (int r = tid; r < A_BLOCKS; r += 512) {
        float2 v = g_ce[r];
        commit += v.x;
        ent    += v.y;
    }
    commit = warp_sum(commit);
    ent    = warp_sum(ent);
    if (lane == 0) { sce[0][w] = commit; sce[1][w] = ent; }

    // channel sums: warp w (<13) owns channel w: 256 contiguous floats, 8/lane
    if (w < CC) {
        const float4* cp = reinterpret_cast<const float4*>(&g_chsum[w * SLOTS]);
        float4 u0 = cp[lane];            // floats [4*lane, 4*lane+4)
        float4 u1 = cp[lane + 32];       // floats [128+4*lane, ...)
        float chs = (u0.x + u0.y) + (u0.z + u0.w) + (u1.x + u1.y) + (u1.z + u1.w);
        chs = warp_sum(chs);
        if (lane == 0) sch[w] = chs;
    }
    __syncthreads();

    // mean-entropy: 13 lanes of warp 0, parallel fp32 logs
    if (tid < 32) {
        float me = 0.0f;
        if (tid < CC) {
            float mp = sch[tid] * (1.0f / (float)NPIX);
            mp = fminf(fmaxf(mp, 1e-12f), 1.0f - 1e-7f);
            float mq = 1.0f - mp;
            me = -(mp * __logf(mp) + mq * __logf(mq));
        }
        me = warp_sum(me);
        if (tid == 0) sment = me * (1.0f / (float)CC);
    }
    __syncthreads();

    if (tid == 0) {
        float c0 = 0.0f, e0 = 0.0f;
        #pragma unroll
        for (int i = 0; i < 16; i++) { c0 += sce[0][i]; e0 += sce[1][i]; }
        out[NTOT]     = c0 * (float)(1.25 * 0.1 / (double)NTOT);
        out[NTOT + 1] = (e0 * (float)(1.0 / (double)NTOT) - sment) * 0.1f;
    }
}

extern "C" void kernel_launch(void* const* d_in, const int* in_sizes, int n_in,
                              void* d_out, int out_size) {
    const float* z = (const float*)d_in[0];
    float* out = (float*)d_out;
    lfq_planes<<<A_BLOCKS, THREADS>>>(z, out);
    lfq_pack_finalize<<<PACK_BLOCKS + 1, 512>>>(out);
}